// round 7
// baseline (speedup 1.0000x reference)
#include <cuda_runtime.h>

// Problem constants
#define Hdim 512
#define Bdim 256
#define Tdim 1024
#define NCLS 10

// Launch geometry: 8 row-groups x 16 col-groups = 128 CTAs, all resident.
#define NCTA 128
#define TPB  128
#define C_GRID 16
#define HR 64          // rows of h computed per CTA
#define BC 16          // batch columns per CTA
#define PW 514         // smem pitch (floats) for W slice  (conflict-free, 8B aligned)
#define PH 514         // smem pitch (floats) for transposed h block
#define SMEM_BYTES ((HR * PW + BC * PH) * 4)   // 164,480 B

// Persistent state: double-buffered hidden state + grid barrier counter.
__device__ float g_h[2][Hdim * Bdim];
__device__ unsigned int g_bar;

// Packed fp32x2 FMA (Blackwell): 2 FMA per instruction on the fma pipe.
__device__ __forceinline__ void fma2(unsigned long long& acc,
                                     unsigned long long a,
                                     unsigned long long b) {
    asm("fma.rn.f32x2 %0, %1, %2, %0;" : "+l"(acc) : "l"(a), "l"(b));
}

__global__ void __launch_bounds__(TPB, 1)
rnn_persistent(const float* __restrict__ x,       // [B, T]
               const float* __restrict__ h_init,  // [H]
               const float* __restrict__ W_hx,    // [H]
               const float* __restrict__ W_hh,    // [H, H]
               const float* __restrict__ b_h,     // [H]
               const float* __restrict__ W_ph,    // [NCLS, H]
               const float* __restrict__ b_p,     // [NCLS]
               float* __restrict__ out)           // [B, NCLS]
{
    extern __shared__ float smem[];
    float* sW = smem;                 // [HR][PW]  W_hh row-slice
    float* sH = smem + HR * PW;       // [BC][PH]  transposed h block (hT[c][k])

    const int cta = blockIdx.x;
    const int tid = threadIdx.x;
    const int rg = cta / C_GRID;
    const int cg = cta % C_GRID;
    const int rBase = rg * HR;
    const int cBase = cg * BC;

    // ---- One-time: load W_hh slice (rows rBase..rBase+HR) into smem ----
    for (int i = tid; i < HR * (Hdim / 4); i += TPB) {
        int r  = i >> 7;          // Hdim/4 == 128
        int k4 = i & 127;
        float4 v = reinterpret_cast<const float4*>(W_hh + (rBase + r) * Hdim)[k4];
        float* d = sW + r * PW + (k4 << 2);
        d[0] = v.x; d[1] = v.y; d[2] = v.z; d[3] = v.w;
    }

    // ---- One-time: init h buffer 0 with broadcast h_init (disjoint ranges) ----
    {
        const int per  = (Hdim * Bdim) / NCTA;   // 1024
        const int base = cta * per;
        for (int i = tid; i < per; i += TPB) {
            int e = base + i;
            __stcg(&g_h[0][e], h_init[e >> 8]);  // e / Bdim
        }
    }

    // ---- Per-thread tile: 4 rows x 2 cols, f32x2-paired over k ----
    const int lane = tid & 31;
    const int wrp  = tid >> 5;
    const int trg  = wrp * 4 + (lane >> 3);   // thread-row group 0..15
    const int tc   = lane & 7;                // thread-col 0..7
    const int r0   = trg * 4;                 // local rows r0..r0+3
    const int c0   = tc * 2;                  // local cols c0, c0+1

    float whx[4], bh[4];
#pragma unroll
    for (int i = 0; i < 4; i++) {
        whx[i] = W_hx[rBase + r0 + i];
        bh[i]  = b_h[rBase + r0 + i];
    }
    const float* xr0 = x + (cBase + c0) * Tdim;
    const float* xr1 = xr0 + Tdim;

    const unsigned long long* wp0 = reinterpret_cast<const unsigned long long*>(sW + (r0 + 0) * PW);
    const unsigned long long* wp1 = reinterpret_cast<const unsigned long long*>(sW + (r0 + 1) * PW);
    const unsigned long long* wp2 = reinterpret_cast<const unsigned long long*>(sW + (r0 + 2) * PW);
    const unsigned long long* wp3 = reinterpret_cast<const unsigned long long*>(sW + (r0 + 3) * PW);
    const unsigned long long* hp0 = reinterpret_cast<const unsigned long long*>(sH + (c0 + 0) * PH);
    const unsigned long long* hp1 = reinterpret_cast<const unsigned long long*>(sH + (c0 + 1) * PH);

    unsigned int target = NCTA;

    // Grid barrier: store -> fence -> bar -> (t0) release arrive + acquire spin -> bar
#define GRID_SYNC()                                                   \
    do {                                                              \
        __threadfence();                                              \
        __syncthreads();                                              \
        if (tid == 0) {                                               \
            atomicAdd(&g_bar, 1u);                                    \
            while (*(volatile unsigned int*)&g_bar < target) { }      \
            __threadfence();                                          \
        }                                                             \
        __syncthreads();                                              \
        target += NCTA;                                               \
    } while (0)

    GRID_SYNC();   // W slice + h0 init visible everywhere

    for (int t = 0; t < Tdim; t++) {
        const float* hc = g_h[t & 1];
        float*       hn = g_h[(t + 1) & 1];

        // Load this CTA's h column-block, transposed, L1-bypassed.
        // STS pattern is bank-conflict-free (bank = (2*cc + k) mod 32).
        for (int i = tid; i < Hdim * BC; i += TPB) {
            int cc = i & (BC - 1);
            int k  = i >> 4;
            sH[cc * PH + k] = __ldcg(hc + k * Bdim + cBase + cc);
        }
        __syncthreads();

        unsigned long long acc00 = 0ull, acc01 = 0ull;
        unsigned long long acc10 = 0ull, acc11 = 0ull;
        unsigned long long acc20 = 0ull, acc21 = 0ull;
        unsigned long long acc30 = 0ull, acc31 = 0ull;

#pragma unroll 8
        for (int k2 = 0; k2 < Hdim / 2; k2++) {
            unsigned long long hv0 = hp0[k2];
            unsigned long long hv1 = hp1[k2];
            unsigned long long w0  = wp0[k2];
            unsigned long long w1  = wp1[k2];
            unsigned long long w2  = wp2[k2];
            unsigned long long w3  = wp3[k2];
            fma2(acc00, w0, hv0);  fma2(acc01, w0, hv1);
            fma2(acc10, w1, hv0);  fma2(acc11, w1, hv1);
            fma2(acc20, w2, hv0);  fma2(acc21, w2, hv1);
            fma2(acc30, w3, hv0);  fma2(acc31, w3, hv1);
        }

        const float xv0 = xr0[t];
        const float xv1 = xr1[t];
        float* hrow = hn + (rBase + r0) * Bdim + cBase + c0;

        {
            unsigned long long aAarr[4] = {acc00, acc10, acc20, acc30};
            unsigned long long aBarr[4] = {acc01, acc11, acc21, acc31};
#pragma unroll
            for (int i = 0; i < 4; i++) {
                float2 aA = *reinterpret_cast<float2*>(&aAarr[i]);
                float2 aB = *reinterpret_cast<float2*>(&aBarr[i]);
                float sA = (aA.x + aA.y) + whx[i] * xv0 + bh[i];
                float sB = (aB.x + aB.y) + whx[i] * xv1 + bh[i];
                __stcg(hrow + i * Bdim + 0, tanhf(sA));
                __stcg(hrow + i * Bdim + 1, tanhf(sB));
            }
        }

        GRID_SYNC();   // also guards sH reuse next iteration
    }

    // ---- Final projection: p.T[b][n] = W_ph[n,:] @ h_last[:,b] + b_p[n] ----
    // T even -> h_last lives in g_h[0]. 128 CTAs x 20 threads = 2560 outputs.
    if (tid < 20) {
        const int o = cta * 20 + tid;        // o = b*NCLS + n
        const int b = o / NCLS;
        const int n = o - b * NCLS;
        const float* wr = W_ph + n * Hdim;
        const float* hf = g_h[0] + b;
        float s = b_p[n];
#pragma unroll 8
        for (int k = 0; k < Hdim; k++)
            s += wr[k] * __ldcg(hf + k * Bdim);
        out[o] = s;
    }
#undef GRID_SYNC
}

extern "C" void kernel_launch(void* const* d_in, const int* in_sizes, int n_in,
                              void* d_out, int out_size) {
    const float* x      = (const float*)d_in[0];
    const float* h_init = (const float*)d_in[1];
    const float* W_hx   = (const float*)d_in[2];
    const float* W_hh   = (const float*)d_in[3];
    const float* b_h    = (const float*)d_in[4];
    const float* W_ph   = (const float*)d_in[5];
    const float* b_p    = (const float*)d_in[6];
    float* out = (float*)d_out;

    cudaFuncSetAttribute(rnn_persistent,
                         cudaFuncAttributeMaxDynamicSharedMemorySize, SMEM_BYTES);

    // Reset the grid-barrier counter every launch (graph-capturable, no allocs).
    void* barp = nullptr;
    cudaGetSymbolAddress(&barp, g_bar);
    cudaMemsetAsync(barp, 0, sizeof(unsigned int), 0);

    rnn_persistent<<<NCTA, TPB, SMEM_BYTES, 0>>>(x, h_init, W_hx, W_hh,
                                                 b_h, W_ph, b_p, out);
}